// round 1
// baseline (speedup 1.0000x reference)
#include <cuda_runtime.h>
#include <cstdint>

#define NV   4096
#define DV   512
#define F1V  64
#define HV   4
#define HF   256   // H*F1
#define F2V  32
#define F3V  16
#define MAXNZ 128
#define ALPHA 0.2f

// ---------------- scratch (device globals; no allocs allowed) ----------------
__device__ int   g_col[NV * MAXNZ];
__device__ int   g_cnt[NV];
__device__ float g_Whcat[NV * HF];   // x @ W_heads (head h in cols [h*64,(h+1)*64))
__device__ float g_cat[NV * HF];     // multi-head GAT output (elu'd, concat)
__device__ float g_Whc[NV * F1V];    // cat @ W_att
__device__ float g_el[HV * NV];
__device__ float g_er[HV * NV];
__device__ float g_el2[NV];
__device__ float g_er2[NV];
__device__ float g_gc[NV * F1V];     // attention-level GAT output
__device__ float g_t1[NV * F2V];
__device__ float g_h1[NV * F2V];
__device__ float g_t23[NV * 32];     // [mu-pre | logvar-pre] per row (16+16)
__device__ float g_z[NV * F3V];

// ---------------- CSR build: deterministic in-order compaction ---------------
__global__ void k_csr(const float* __restrict__ adj) {
    int i = blockIdx.x;
    const float* row = adj + (size_t)i * NV;
    __shared__ int warp_cnt[8];
    __shared__ int offs[8];
    __shared__ int base_s;
    int tid = threadIdx.x, wid = tid >> 5, lane = tid & 31;
    if (tid == 0) base_s = 0;
    __syncthreads();
    for (int c0 = 0; c0 < NV; c0 += 256) {
        float v = row[c0 + tid];
        bool p = v > 0.f;
        unsigned bal = __ballot_sync(0xffffffffu, p);
        if (lane == 0) warp_cnt[wid] = __popc(bal);
        __syncthreads();
        if (tid == 0) {
            int b = base_s;
            for (int w = 0; w < 8; w++) { offs[w] = b; b += warp_cnt[w]; }
            base_s = b;
        }
        __syncthreads();
        if (p) {
            int pos = offs[wid] + __popc(bal & ((1u << lane) - 1u));
            if (pos < MAXNZ) g_col[i * MAXNZ + pos] = c0 + tid;
        }
    }
    if (tid == 0) g_cnt[i] = (base_s < MAXNZ) ? base_s : MAXNZ;
}

// ---------------- tiled FP32 GEMM: C[64-col tile] = A[M,K] @ B[K,64] ---------
// blockIdx.y = batch (head); Bh = B + h*bstride; C col offset = h*ccoloff.
__global__ void k_gemm64(const float* __restrict__ A, const float* __restrict__ Bbase,
                         float* __restrict__ Cbase, int K, int ldc, int bstride, int ccoloff) {
    int h = blockIdx.y;
    const float* B = Bbase + (size_t)h * bstride;
    int m0 = blockIdx.x * 64;
    int tid = threadIdx.x;
    int tx = tid & 15, ty = tid >> 4;
    __shared__ float As[16][64];   // [k][m]
    __shared__ float Bs[16][64];   // [k][n]
    float acc[4][4] = {};
    for (int k0 = 0; k0 < K; k0 += 16) {
        {   // A tile 64x16 -> transposed store
            int idx = tid * 4;
            int r = idx >> 4, c = idx & 15;
            float4 v = *(const float4*)(A + (size_t)(m0 + r) * K + k0 + c);
            As[c][r] = v.x; As[c + 1][r] = v.y; As[c + 2][r] = v.z; As[c + 3][r] = v.w;
        }
        {   // B tile 16x64
            int idx = tid * 4;
            int r = idx >> 6, c = idx & 63;
            float4 v = *(const float4*)(B + (size_t)(k0 + r) * 64 + c);
            *(float4*)&Bs[r][c] = v;
        }
        __syncthreads();
#pragma unroll
        for (int kk = 0; kk < 16; kk++) {
            float4 a = *(float4*)&As[kk][ty * 4];
            float4 b = *(float4*)&Bs[kk][tx * 4];
            acc[0][0] += a.x * b.x; acc[0][1] += a.x * b.y; acc[0][2] += a.x * b.z; acc[0][3] += a.x * b.w;
            acc[1][0] += a.y * b.x; acc[1][1] += a.y * b.y; acc[1][2] += a.y * b.z; acc[1][3] += a.y * b.w;
            acc[2][0] += a.z * b.x; acc[2][1] += a.z * b.y; acc[2][2] += a.z * b.z; acc[2][3] += a.z * b.w;
            acc[3][0] += a.w * b.x; acc[3][1] += a.w * b.y; acc[3][2] += a.w * b.z; acc[3][3] += a.w * b.w;
        }
        __syncthreads();
    }
    int coff = h * ccoloff;
#pragma unroll
    for (int i = 0; i < 4; i++) {
        float4 st = make_float4(acc[i][0], acc[i][1], acc[i][2], acc[i][3]);
        *(float4*)(Cbase + (size_t)(m0 + ty * 4 + i) * ldc + coff + tx * 4) = st;
    }
}

// ---------------- el/er: warp-per-(h,i) dot of Wh row with attention vec -----
__global__ void k_elr(const float* __restrict__ Wh, const float* __restrict__ a,
                      float* __restrict__ el, float* __restrict__ er,
                      int Hn, int Fdim, int rowstride) {
    int warp = (blockIdx.x * blockDim.x + threadIdx.x) >> 5;
    int lane = threadIdx.x & 31;
    if (warp >= Hn * NV) return;
    int h = warp / NV, i = warp % NV;
    const float* wrow = Wh + (size_t)i * rowstride + h * Fdim;
    const float* ah = a + h * 2 * Fdim;
    float s1 = 0.f, s2 = 0.f;
    for (int f = lane; f < Fdim; f += 32) {
        float w = wrow[f];
        s1 += w * ah[f];
        s2 += w * ah[Fdim + f];
    }
#pragma unroll
    for (int o = 16; o > 0; o >>= 1) {
        s1 += __shfl_xor_sync(0xffffffffu, s1, o);
        s2 += __shfl_xor_sync(0xffffffffu, s2, o);
    }
    if (lane == 0) { el[h * NV + i] = s1; er[h * NV + i] = s2; }
}

// ---------------- GAT: masked softmax over neighbors + aggregate + elu ------
template <int HH, int FF>
__global__ void k_gat(const float* __restrict__ Wh, const float* __restrict__ el,
                      const float* __restrict__ er, float* __restrict__ out) {
    const int NT = HH * FF;
    int i = blockIdx.x;
    __shared__ int cols_s[MAXNZ];
    __shared__ float ew[HH][MAXNZ];
    int cnt = g_cnt[i];
    int tid = threadIdx.x;
    for (int k = tid; k < cnt; k += NT) cols_s[k] = g_col[i * MAXNZ + k];
    __syncthreads();
    for (int k = tid; k < cnt; k += NT) {
        int j = cols_s[k];
#pragma unroll
        for (int h = 0; h < HH; h++) {
            float e = el[h * NV + i] + er[h * NV + j];
            e = (e >= 0.f) ? e : ALPHA * e;
            ew[h][k] = e;
        }
    }
    __syncthreads();
    if (tid < HH) {
        float m = -1e30f;
        for (int k = 0; k < cnt; k++) m = fmaxf(m, ew[tid][k]);
        float s = 0.f;
        for (int k = 0; k < cnt; k++) { float v = __expf(ew[tid][k] - m); ew[tid][k] = v; s += v; }
        float inv = 1.f / s;
        for (int k = 0; k < cnt; k++) ew[tid][k] *= inv;
    }
    __syncthreads();
    int h = tid / FF;
    float a0 = 0.f, a1 = 0.f, a2 = 0.f, a3 = 0.f;
    int k = 0;
    for (; k + 4 <= cnt; k += 4) {
        a0 += ew[h][k]     * Wh[(size_t)cols_s[k] * NT + tid];
        a1 += ew[h][k + 1] * Wh[(size_t)cols_s[k + 1] * NT + tid];
        a2 += ew[h][k + 2] * Wh[(size_t)cols_s[k + 2] * NT + tid];
        a3 += ew[h][k + 3] * Wh[(size_t)cols_s[k + 3] * NT + tid];
    }
    for (; k < cnt; k++) a0 += ew[h][k] * Wh[(size_t)cols_s[k] * NT + tid];
    float acc = (a0 + a1) + (a2 + a3);
    out[(size_t)i * NT + tid] = (acc > 0.f) ? acc : (__expf(acc) - 1.f);
}

// ---------------- small dense layers ----------------------------------------
__global__ void k_t1(const float* __restrict__ A, const float* __restrict__ W1) {
    __shared__ float Bs[64 * 32];
    int tid = threadIdx.x;
    for (int idx = tid; idx < 64 * 32; idx += 256) Bs[idx] = W1[idx];
    __syncthreads();
    int r = blockIdx.x * 8 + (tid >> 5);
    int c = tid & 31;
    float acc = 0.f;
    const float* ar = A + (size_t)r * 64;
#pragma unroll 8
    for (int k = 0; k < 64; k++) acc += ar[k] * Bs[k * 32 + c];
    g_t1[r * 32 + c] = acc;
}

__global__ void k_t23(const float* __restrict__ W2, const float* __restrict__ W3) {
    __shared__ float Bs[32 * 32];
    int tid = threadIdx.x;
    for (int idx = tid; idx < 32 * 16; idx += 256) {
        int k = idx >> 4, c = idx & 15;
        Bs[k * 32 + c]      = W2[idx];
        Bs[k * 32 + 16 + c] = W3[idx];
    }
    __syncthreads();
    int r = blockIdx.x * 8 + (tid >> 5);
    int c = tid & 31;
    float acc = 0.f;
    const float* ar = g_h1 + (size_t)r * 32;
#pragma unroll 8
    for (int k = 0; k < 32; k++) acc += ar[k] * Bs[k * 32 + c];
    g_t23[r * 32 + c] = acc;
}

// ---------------- spmm (adj @ X) kernels -------------------------------------
__global__ void k_spmm_relu() {
    int tid = threadIdx.x;
    int r = blockIdx.x * 8 + (tid >> 5);
    int lane = tid & 31;
    int cnt = g_cnt[r];
    const int* cp = g_col + r * MAXNZ;
    float acc = 0.f;
    int k = 0;
    for (; k + 4 <= cnt; k += 4) {
        int j0 = cp[k], j1 = cp[k + 1], j2 = cp[k + 2], j3 = cp[k + 3];
        acc += g_t1[j0 * 32 + lane] + g_t1[j1 * 32 + lane]
             + g_t1[j2 * 32 + lane] + g_t1[j3 * 32 + lane];
    }
    for (; k < cnt; k++) acc += g_t1[cp[k] * 32 + lane];
    g_h1[r * 32 + lane] = fmaxf(acc, 0.f);
}

__global__ void k_mlz(const float* __restrict__ eps, float* __restrict__ out) {
    int tid = threadIdx.x;
    int r = blockIdx.x * 8 + (tid >> 5);
    int lane = tid & 31;
    int cnt = g_cnt[r];
    const int* cp = g_col + r * MAXNZ;
    float acc = 0.f;
    int k = 0;
    for (; k + 4 <= cnt; k += 4) {
        int j0 = cp[k], j1 = cp[k + 1], j2 = cp[k + 2], j3 = cp[k + 3];
        acc += g_t23[j0 * 32 + lane] + g_t23[j1 * 32 + lane]
             + g_t23[j2 * 32 + lane] + g_t23[j3 * 32 + lane];
    }
    for (; k < cnt; k++) acc += g_t23[cp[k] * 32 + lane];
    float other = __shfl_xor_sync(0xffffffffu, acc, 16);
    const size_t NN = (size_t)NV * NV;
    if (lane < 16) {
        float mu = acc, lv = other;
        float z = eps[r * 16 + lane] * expf(lv) + mu;
        g_z[r * 16 + lane] = z;
        out[NN + (size_t)r * 16 + lane] = mu;
    } else {
        out[NN + (size_t)NV * 16 + (size_t)r * 16 + (lane - 16)] = acc;
    }
}

// ---------------- adj_rec = z @ z^T ------------------------------------------
__global__ void k_zz(float* __restrict__ out) {
    int m0 = blockIdx.y * 64, n0 = blockIdx.x * 64;
    __shared__ float zr[16][64];
    __shared__ float zc[16][64];
    int tid = threadIdx.x;
    {
        int idx = tid * 4;
        int r = idx >> 4, c = idx & 15;
        float4 v = *(const float4*)&g_z[(size_t)(m0 + r) * 16 + c];
        zr[c][r] = v.x; zr[c + 1][r] = v.y; zr[c + 2][r] = v.z; zr[c + 3][r] = v.w;
        float4 w = *(const float4*)&g_z[(size_t)(n0 + r) * 16 + c];
        zc[c][r] = w.x; zc[c + 1][r] = w.y; zc[c + 2][r] = w.z; zc[c + 3][r] = w.w;
    }
    __syncthreads();
    int tx = tid & 15, ty = tid >> 4;
    float acc[4][4] = {};
#pragma unroll
    for (int k = 0; k < 16; k++) {
        float4 a = *(float4*)&zr[k][ty * 4];
        float4 b = *(float4*)&zc[k][tx * 4];
        acc[0][0] += a.x * b.x; acc[0][1] += a.x * b.y; acc[0][2] += a.x * b.z; acc[0][3] += a.x * b.w;
        acc[1][0] += a.y * b.x; acc[1][1] += a.y * b.y; acc[1][2] += a.y * b.z; acc[1][3] += a.y * b.w;
        acc[2][0] += a.z * b.x; acc[2][1] += a.z * b.y; acc[2][2] += a.z * b.z; acc[2][3] += a.z * b.w;
        acc[3][0] += a.w * b.x; acc[3][1] += a.w * b.y; acc[3][2] += a.w * b.z; acc[3][3] += a.w * b.w;
    }
#pragma unroll
    for (int i = 0; i < 4; i++) {
        float4 st = make_float4(acc[i][0], acc[i][1], acc[i][2], acc[i][3]);
        *(float4*)(out + (size_t)(m0 + ty * 4 + i) * NV + n0 + tx * 4) = st;
    }
}

// ---------------- launch ------------------------------------------------------
extern "C" void kernel_launch(void* const* d_in, const int* in_sizes, int n_in,
                              void* d_out, int out_size) {
    const float* x       = (const float*)d_in[0];
    const float* adj     = (const float*)d_in[1];
    const float* W_heads = (const float*)d_in[2];
    const float* a_heads = (const float*)d_in[3];
    const float* W_att   = (const float*)d_in[4];
    const float* a_att   = (const float*)d_in[5];
    const float* W1      = (const float*)d_in[6];
    const float* W2      = (const float*)d_in[7];
    const float* W3      = (const float*)d_in[8];
    const float* eps     = (const float*)d_in[9];
    float* out = (float*)d_out;

    float *p_Whcat, *p_cat, *p_Whc, *p_el, *p_er, *p_el2, *p_er2, *p_gc;
    cudaGetSymbolAddress((void**)&p_Whcat, g_Whcat);
    cudaGetSymbolAddress((void**)&p_cat,   g_cat);
    cudaGetSymbolAddress((void**)&p_Whc,   g_Whc);
    cudaGetSymbolAddress((void**)&p_el,    g_el);
    cudaGetSymbolAddress((void**)&p_er,    g_er);
    cudaGetSymbolAddress((void**)&p_el2,   g_el2);
    cudaGetSymbolAddress((void**)&p_er2,   g_er2);
    cudaGetSymbolAddress((void**)&p_gc,    g_gc);

    // 1. CSR of adj
    k_csr<<<NV, 256>>>(adj);
    // 2. Wh for all heads -> g_Whcat [N, 256]
    k_gemm64<<<dim3(NV / 64, HV), 256>>>(x, W_heads, p_Whcat, DV, HF, DV * F1V, F1V);
    // 3. el/er per head
    k_elr<<<(HV * NV * 32) / 256, 256>>>(p_Whcat, a_heads, p_el, p_er, HV, F1V, HF);
    // 4. multi-head GAT aggregate -> g_cat
    k_gat<HV, F1V><<<NV, HV * F1V>>>(p_Whcat, p_el, p_er, p_cat);
    // 5. Whc = cat @ W_att
    k_gemm64<<<dim3(NV / 64, 1), 256>>>(p_cat, W_att, p_Whc, HF, F1V, 0, 0);
    // 6. el2/er2
    k_elr<<<(NV * 32) / 256, 256>>>(p_Whc, a_att, p_el2, p_er2, 1, F1V, F1V);
    // 7. attention-level GAT -> g_gc
    k_gat<1, F1V><<<NV, F1V>>>(p_Whc, p_el2, p_er2, p_gc);
    // 8. t1 = gc @ W1
    k_t1<<<NV / 8, 256>>>(p_gc, W1);
    // 9. h1 = relu(adj @ t1)
    k_spmm_relu<<<NV / 8, 256>>>();
    // 10. t23 = h1 @ [W2 | W3]
    k_t23<<<NV / 8, 256>>>(W2, W3);
    // 11. mu/logvar = adj @ t23 ; z = eps*exp(logvar)+mu ; write mu/logvar
    k_mlz<<<NV / 8, 256>>>(eps, out);
    // 12. adj_rec = z @ z^T
    k_zz<<<dim3(NV / 64, NV / 64), 256>>>(out);
}

// round 2
// speedup vs baseline: 1.1864x; 1.1864x over previous
#include <cuda_runtime.h>
#include <cstdint>

#define NV   4096
#define DV   512
#define F1V  64
#define HV   4
#define HF   256   // H*F1
#define F2V  32
#define F3V  16
#define MAXNZ 128
#define ALPHA 0.2f

// ---------------- scratch (device globals; no allocs allowed) ----------------
__device__ int   g_col[NV * MAXNZ];
__device__ int   g_cnt[NV];
__device__ float g_Whcat[NV * HF];   // x @ W_heads (head h in cols [h*64,(h+1)*64))
__device__ float g_cat[NV * HF];     // multi-head GAT output (elu'd, concat)
__device__ float g_Whc[NV * F1V];    // cat @ W_att
__device__ float g_el[HV * NV];
__device__ float g_er[HV * NV];
__device__ float g_el2[NV];
__device__ float g_er2[NV];
__device__ float g_gc[NV * F1V];     // attention-level GAT output
__device__ float g_t1[NV * F2V];
__device__ float g_h1[NV * F2V];
__device__ float g_t23[NV * 32];     // [mu-pre | logvar-pre] per row (16+16)
__device__ float g_z[NV * F3V];

// ---------------- f32x2 packed-FMA helpers (ptxas won't auto-fuse) -----------
__device__ __forceinline__ unsigned long long pack2(float lo, float hi) {
    unsigned long long r;
    asm("mov.b64 %0, {%1, %2};" : "=l"(r) : "f"(lo), "f"(hi));
    return r;
}
__device__ __forceinline__ void ffma2(unsigned long long& d, unsigned long long a,
                                      unsigned long long b) {
    asm("fma.rn.f32x2 %0, %1, %2, %0;" : "+l"(d) : "l"(a), "l"(b));
}
__device__ __forceinline__ float2 unpack2(unsigned long long v) {
    float2 f;
    asm("mov.b64 {%0, %1}, %2;" : "=f"(f.x), "=f"(f.y) : "l"(v));
    return f;
}

// ---------------- CSR build: warp per row, float4 stream, no block syncs -----
__global__ void k_csr(const float* __restrict__ adj) {
    int wid = threadIdx.x >> 5, lane = threadIdx.x & 31;
    int row = blockIdx.x * 8 + wid;
    const float4* r4 = (const float4*)(adj + (size_t)row * NV);
    unsigned lm = (1u << lane) - 1u;
    int base = 0;
    int* cp = g_col + row * MAXNZ;
#pragma unroll 4
    for (int c0 = 0; c0 < NV / 4; c0 += 32) {
        float4 v = r4[c0 + lane];
        unsigned b0 = __ballot_sync(0xffffffffu, v.x > 0.f);
        unsigned b1 = __ballot_sync(0xffffffffu, v.y > 0.f);
        unsigned b2 = __ballot_sync(0xffffffffu, v.z > 0.f);
        unsigned b3 = __ballot_sync(0xffffffffu, v.w > 0.f);
        int t0 = __popc(b0), t1 = __popc(b1), t2 = __popc(b2), t3 = __popc(b3);
        int col = (c0 + lane) * 4;
        if (v.x > 0.f) { int p = base + __popc(b0 & lm);                if (p < MAXNZ) cp[p] = col; }
        if (v.y > 0.f) { int p = base + t0 + __popc(b1 & lm);           if (p < MAXNZ) cp[p] = col + 1; }
        if (v.z > 0.f) { int p = base + t0 + t1 + __popc(b2 & lm);      if (p < MAXNZ) cp[p] = col + 2; }
        if (v.w > 0.f) { int p = base + t0 + t1 + t2 + __popc(b3 & lm); if (p < MAXNZ) cp[p] = col + 3; }
        base += t0 + t1 + t2 + t3;
    }
    if (lane == 0) g_cnt[row] = (base < MAXNZ) ? base : MAXNZ;
}

// ---------------- GEMM: C[64-col tile per head] = A[M,K] @ B[K,64] -----------
// 128 threads, tile BM=64 x BN=64, BK=16, micro 8x4, f32x2 accumulators.
__global__ __launch_bounds__(128) void k_gemm(const float* __restrict__ A,
                                              const float* __restrict__ Bbase,
                                              float* __restrict__ Cbase,
                                              int K, int ldc, int bstride, int ccoloff) {
    int h = blockIdx.y;
    const float* B = Bbase + (size_t)h * bstride;
    int m0 = blockIdx.x * 64;
    int tid = threadIdx.x;
    int tx = tid & 15, ty = tid >> 4;        // ty 0..7 -> rows ty*8 ; tx -> cols tx*4
    __shared__ float As[16][64];             // [k][m]
    __shared__ float Bs[16][64];             // [k][n]
    unsigned long long acc2[8][2] = {};
    for (int k0 = 0; k0 < K; k0 += 16) {
#pragma unroll
        for (int t = tid; t < 256; t += 128) {   // A tile 64x16 -> transposed
            int r = t >> 2, c4 = (t & 3) * 4;
            float4 v = *(const float4*)(A + (size_t)(m0 + r) * K + k0 + c4);
            As[c4][r] = v.x; As[c4 + 1][r] = v.y; As[c4 + 2][r] = v.z; As[c4 + 3][r] = v.w;
        }
#pragma unroll
        for (int t = tid; t < 256; t += 128) {   // B tile 16x64
            int r = t >> 4, c = (t & 15) * 4;
            *(float4*)&Bs[r][c] = *(const float4*)(B + (size_t)(k0 + r) * 64 + c);
        }
        __syncthreads();
#pragma unroll
        for (int kk = 0; kk < 16; kk++) {
            float4 b = *(float4*)&Bs[kk][tx * 4];
            unsigned long long b01 = pack2(b.x, b.y), b23 = pack2(b.z, b.w);
            float4 a0 = *(float4*)&As[kk][ty * 8];
            float4 a1 = *(float4*)&As[kk][ty * 8 + 4];
            float av[8] = {a0.x, a0.y, a0.z, a0.w, a1.x, a1.y, a1.z, a1.w};
#pragma unroll
            for (int i = 0; i < 8; i++) {
                unsigned long long ai = pack2(av[i], av[i]);
                ffma2(acc2[i][0], ai, b01);
                ffma2(acc2[i][1], ai, b23);
            }
        }
        __syncthreads();
    }
    int coff = h * ccoloff;
#pragma unroll
    for (int i = 0; i < 8; i++) {
        float2 c0 = unpack2(acc2[i][0]), c1 = unpack2(acc2[i][1]);
        *(float4*)(Cbase + (size_t)(m0 + ty * 8 + i) * ldc + coff + tx * 4)
            = make_float4(c0.x, c0.y, c1.x, c1.y);
    }
}

// ---------------- el/er: warp-per-(h,i) dot of Wh row with attention vec -----
__global__ void k_elr(const float* __restrict__ Wh, const float* __restrict__ a,
                      float* __restrict__ el, float* __restrict__ er,
                      int Hn, int Fdim, int rowstride) {
    int warp = (blockIdx.x * blockDim.x + threadIdx.x) >> 5;
    int lane = threadIdx.x & 31;
    if (warp >= Hn * NV) return;
    int h = warp / NV, i = warp % NV;
    const float* wrow = Wh + (size_t)i * rowstride + h * Fdim;
    const float* ah = a + h * 2 * Fdim;
    float s1 = 0.f, s2 = 0.f;
    for (int f = lane; f < Fdim; f += 32) {
        float w = wrow[f];
        s1 += w * ah[f];
        s2 += w * ah[Fdim + f];
    }
#pragma unroll
    for (int o = 16; o > 0; o >>= 1) {
        s1 += __shfl_xor_sync(0xffffffffu, s1, o);
        s2 += __shfl_xor_sync(0xffffffffu, s2, o);
    }
    if (lane == 0) { el[h * NV + i] = s1; er[h * NV + i] = s2; }
}

// ---------------- GAT: warp-parallel softmax + float4 gather aggregate -------
template <int HH>
__global__ void k_gat(const float* __restrict__ Wh, const float* __restrict__ el,
                      const float* __restrict__ er, float* __restrict__ out) {
    const int NT = HH * 64;          // threads
    const int QN = HH * 16;          // float4 per row
    int i = blockIdx.x;
    __shared__ int cols_s[MAXNZ];
    __shared__ float ew[HH][MAXNZ];
    __shared__ float4 red[NT];
    int cnt = g_cnt[i];
    int tid = threadIdx.x;
    for (int k = tid; k < cnt; k += NT) cols_s[k] = g_col[i * MAXNZ + k];
    __syncthreads();
    for (int k = tid; k < cnt; k += NT) {
        int j = cols_s[k];
#pragma unroll
        for (int h = 0; h < HH; h++) {
            float e = el[h * NV + i] + er[h * NV + j];
            ew[h][k] = (e >= 0.f) ? e : ALPHA * e;
        }
    }
    __syncthreads();
    int wid = tid >> 5, lane = tid & 31;
    if (wid < HH) {
        float m = -1e30f;
        for (int k = lane; k < cnt; k += 32) m = fmaxf(m, ew[wid][k]);
#pragma unroll
        for (int o = 16; o > 0; o >>= 1) m = fmaxf(m, __shfl_xor_sync(0xffffffffu, m, o));
        float s = 0.f;
        for (int k = lane; k < cnt; k += 32) {
            float v = __expf(ew[wid][k] - m);
            ew[wid][k] = v; s += v;
        }
#pragma unroll
        for (int o = 16; o > 0; o >>= 1) s += __shfl_xor_sync(0xffffffffu, s, o);
        float inv = 1.f / s;
        for (int k = lane; k < cnt; k += 32) ew[wid][k] *= inv;
    }
    __syncthreads();
    int q = tid & (QN - 1);          // float4 column index
    int p = tid / QN;                // phase 0..3
    int h = q >> 4;                  // 16 float4 per head
    const float4* Wh4 = (const float4*)Wh;
    float4 acc = make_float4(0.f, 0.f, 0.f, 0.f);
    for (int k = p; k < cnt; k += 4) {
        float w = ew[h][k];
        float4 v = Wh4[(size_t)cols_s[k] * QN + q];
        acc.x += w * v.x; acc.y += w * v.y; acc.z += w * v.z; acc.w += w * v.w;
    }
    red[tid] = acc;
    __syncthreads();
    if (tid < QN) {
        float4 a = red[tid], b = red[tid + QN], c = red[tid + 2 * QN], d = red[tid + 3 * QN];
        float4 s = make_float4(a.x + b.x + c.x + d.x, a.y + b.y + c.y + d.y,
                               a.z + b.z + c.z + d.z, a.w + b.w + c.w + d.w);
        s.x = (s.x > 0.f) ? s.x : (__expf(s.x) - 1.f);
        s.y = (s.y > 0.f) ? s.y : (__expf(s.y) - 1.f);
        s.z = (s.z > 0.f) ? s.z : (__expf(s.z) - 1.f);
        s.w = (s.w > 0.f) ? s.w : (__expf(s.w) - 1.f);
        ((float4*)out)[(size_t)i * QN + tid] = s;
    }
}

// ---------------- small dense layers ----------------------------------------
__global__ void k_t1(const float* __restrict__ A, const float* __restrict__ W1) {
    __shared__ float Bs[64 * 32];
    int tid = threadIdx.x;
    for (int idx = tid; idx < 64 * 32; idx += 256) Bs[idx] = W1[idx];
    __syncthreads();
    int r = blockIdx.x * 8 + (tid >> 5);
    int c = tid & 31;
    float acc = 0.f;
    const float* ar = A + (size_t)r * 64;
#pragma unroll 8
    for (int k = 0; k < 64; k++) acc += ar[k] * Bs[k * 32 + c];
    g_t1[r * 32 + c] = acc;
}

__global__ void k_t23(const float* __restrict__ W2, const float* __restrict__ W3) {
    __shared__ float Bs[32 * 32];
    int tid = threadIdx.x;
    for (int idx = tid; idx < 32 * 16; idx += 256) {
        int k = idx >> 4, c = idx & 15;
        Bs[k * 32 + c]      = W2[idx];
        Bs[k * 32 + 16 + c] = W3[idx];
    }
    __syncthreads();
    int r = blockIdx.x * 8 + (tid >> 5);
    int c = tid & 31;
    float acc = 0.f;
    const float* ar = g_h1 + (size_t)r * 32;
#pragma unroll 8
    for (int k = 0; k < 32; k++) acc += ar[k] * Bs[k * 32 + c];
    g_t23[r * 32 + c] = acc;
}

// ---------------- spmm (adj @ X) kernels -------------------------------------
__global__ void k_spmm_relu() {
    int tid = threadIdx.x;
    int r = blockIdx.x * 8 + (tid >> 5);
    int lane = tid & 31;
    int cnt = g_cnt[r];
    const int* cp = g_col + r * MAXNZ;
    float acc = 0.f;
    int k = 0;
    for (; k + 4 <= cnt; k += 4) {
        int j0 = cp[k], j1 = cp[k + 1], j2 = cp[k + 2], j3 = cp[k + 3];
        acc += g_t1[j0 * 32 + lane] + g_t1[j1 * 32 + lane]
             + g_t1[j2 * 32 + lane] + g_t1[j3 * 32 + lane];
    }
    for (; k < cnt; k++) acc += g_t1[cp[k] * 32 + lane];
    g_h1[r * 32 + lane] = fmaxf(acc, 0.f);
}

__global__ void k_mlz(const float* __restrict__ eps, float* __restrict__ out) {
    int tid = threadIdx.x;
    int r = blockIdx.x * 8 + (tid >> 5);
    int lane = tid & 31;
    int cnt = g_cnt[r];
    const int* cp = g_col + r * MAXNZ;
    float acc = 0.f;
    int k = 0;
    for (; k + 4 <= cnt; k += 4) {
        int j0 = cp[k], j1 = cp[k + 1], j2 = cp[k + 2], j3 = cp[k + 3];
        acc += g_t23[j0 * 32 + lane] + g_t23[j1 * 32 + lane]
             + g_t23[j2 * 32 + lane] + g_t23[j3 * 32 + lane];
    }
    for (; k < cnt; k++) acc += g_t23[cp[k] * 32 + lane];
    float other = __shfl_xor_sync(0xffffffffu, acc, 16);
    const size_t NN = (size_t)NV * NV;
    if (lane < 16) {
        float mu = acc, lv = other;
        float z = eps[r * 16 + lane] * expf(lv) + mu;
        g_z[r * 16 + lane] = z;
        out[NN + (size_t)r * 16 + lane] = mu;
    } else {
        out[NN + (size_t)NV * 16 + (size_t)r * 16 + (lane - 16)] = acc;
    }
}

// ---------------- adj_rec = z @ z^T : 128x128 tile, 8x8 micro, f32x2 ---------
__global__ __launch_bounds__(256) void k_zz(float* __restrict__ out) {
    int m0 = blockIdx.y * 128, n0 = blockIdx.x * 128;
    __shared__ float zr[16][128];
    __shared__ float zc[16][128];
    int tid = threadIdx.x;
    const float4* z4 = (const float4*)g_z;
#pragma unroll
    for (int t = tid; t < 512; t += 256) {
        int r = t >> 2, c4 = (t & 3) * 4;
        float4 v = z4[(size_t)(m0 + r) * 4 + (t & 3)];
        zr[c4][r] = v.x; zr[c4 + 1][r] = v.y; zr[c4 + 2][r] = v.z; zr[c4 + 3][r] = v.w;
        float4 w = z4[(size_t)(n0 + r) * 4 + (t & 3)];
        zc[c4][r] = w.x; zc[c4 + 1][r] = w.y; zc[c4 + 2][r] = w.z; zc[c4 + 3][r] = w.w;
    }
    __syncthreads();
    int tx = tid & 15, ty = tid >> 4;   // rows ty*8, cols tx*8
    unsigned long long acc2[8][4] = {};
#pragma unroll
    for (int kk = 0; kk < 16; kk++) {
        float4 b0 = *(float4*)&zc[kk][tx * 8];
        float4 b1 = *(float4*)&zc[kk][tx * 8 + 4];
        unsigned long long pb0 = pack2(b0.x, b0.y), pb1 = pack2(b0.z, b0.w);
        unsigned long long pb2 = pack2(b1.x, b1.y), pb3 = pack2(b1.z, b1.w);
        float4 a0 = *(float4*)&zr[kk][ty * 8];
        float4 a1 = *(float4*)&zr[kk][ty * 8 + 4];
        float av[8] = {a0.x, a0.y, a0.z, a0.w, a1.x, a1.y, a1.z, a1.w};
#pragma unroll
        for (int i = 0; i < 8; i++) {
            unsigned long long ai = pack2(av[i], av[i]);
            ffma2(acc2[i][0], ai, pb0);
            ffma2(acc2[i][1], ai, pb1);
            ffma2(acc2[i][2], ai, pb2);
            ffma2(acc2[i][3], ai, pb3);
        }
    }
#pragma unroll
    for (int i = 0; i < 8; i++) {
        float2 c0 = unpack2(acc2[i][0]), c1 = unpack2(acc2[i][1]);
        float2 c2 = unpack2(acc2[i][2]), c3 = unpack2(acc2[i][3]);
        float* op = out + (size_t)(m0 + ty * 8 + i) * NV + n0 + tx * 8;
        *(float4*)op       = make_float4(c0.x, c0.y, c1.x, c1.y);
        *(float4*)(op + 4) = make_float4(c2.x, c2.y, c3.x, c3.y);
    }
}

// ---------------- launch ------------------------------------------------------
extern "C" void kernel_launch(void* const* d_in, const int* in_sizes, int n_in,
                              void* d_out, int out_size) {
    const float* x       = (const float*)d_in[0];
    const float* adj     = (const float*)d_in[1];
    const float* W_heads = (const float*)d_in[2];
    const float* a_heads = (const float*)d_in[3];
    const float* W_att   = (const float*)d_in[4];
    const float* a_att   = (const float*)d_in[5];
    const float* W1      = (const float*)d_in[6];
    const float* W2      = (const float*)d_in[7];
    const float* W3      = (const float*)d_in[8];
    const float* eps     = (const float*)d_in[9];
    float* out = (float*)d_out;

    float *p_Whcat, *p_cat, *p_Whc, *p_el, *p_er, *p_el2, *p_er2, *p_gc;
    cudaGetSymbolAddress((void**)&p_Whcat, g_Whcat);
    cudaGetSymbolAddress((void**)&p_cat,   g_cat);
    cudaGetSymbolAddress((void**)&p_Whc,   g_Whc);
    cudaGetSymbolAddress((void**)&p_el,    g_el);
    cudaGetSymbolAddress((void**)&p_er,    g_er);
    cudaGetSymbolAddress((void**)&p_el2,   g_el2);
    cudaGetSymbolAddress((void**)&p_er2,   g_er2);
    cudaGetSymbolAddress((void**)&p_gc,    g_gc);

    // 1. CSR of adj (warp per row)
    k_csr<<<NV / 8, 256>>>(adj);
    // 2. Wh for all heads -> g_Whcat [N, 256]
    k_gemm<<<dim3(NV / 64, HV), 128>>>(x, W_heads, p_Whcat, DV, HF, DV * F1V, F1V);
    // 3. el/er per head
    k_elr<<<(HV * NV * 32) / 256, 256>>>(p_Whcat, a_heads, p_el, p_er, HV, F1V, HF);
    // 4. multi-head GAT aggregate -> g_cat
    k_gat<HV><<<NV, HV * 64>>>(p_Whcat, p_el, p_er, p_cat);
    // 5. Whc = cat @ W_att
    k_gemm<<<dim3(NV / 64, 1), 128>>>(p_cat, W_att, p_Whc, HF, F1V, 0, 0);
    // 6. el2/er2
    k_elr<<<(NV * 32) / 256, 256>>>(p_Whc, a_att, p_el2, p_er2, 1, F1V, F1V);
    // 7. attention-level GAT -> g_gc
    k_gat<1><<<NV, 64>>>(p_Whc, p_el2, p_er2, p_gc);
    // 8. t1 = gc @ W1
    k_t1<<<NV / 8, 256>>>(p_gc, W1);
    // 9. h1 = relu(adj @ t1)
    k_spmm_relu<<<NV / 8, 256>>>();
    // 10. t23 = h1 @ [W2 | W3]
    k_t23<<<NV / 8, 256>>>(W2, W3);
    // 11. mu/logvar = adj @ t23 ; z = eps*exp(logvar)+mu ; write mu/logvar
    k_mlz<<<NV / 8, 256>>>(eps, out);
    // 12. adj_rec = z @ z^T
    k_zz<<<dim3(NV / 128, NV / 128), 256>>>(out);
}